// round 5
// baseline (speedup 1.0000x reference)
#include <cuda_runtime.h>
#include <math.h>

// Fixed problem shape: image [2, 3, 1080, 1920] float32
#define BB 2
#define CC 3
#define HH 1080
#define WW 1920
#define SH 540   // int(1080 * 0.5)
#define SW 960   // int(1920 * 0.5)

#define NS (BB * SH * SW)   // small-res elements per 1ch stack
#define NF (BB * HH * WW)   // full-res elements per 1ch stack

// ---------------- scratch (static device globals; no allocation) ----------------
__device__ float  g_luma[NS];
__device__ float  g_sxy [2 * NS];
__device__ float  g_edge[NS];
__device__ float  g_edge2[NS];
__device__ float  g_kxy [2 * NS];
__device__ float2 g_grad[NS];     // half-res grad field, interleaved (xg, yg)

// ---------------- helpers ----------------
__device__ __forceinline__ float clampf(float v, float lo, float hi) {
    return fminf(fmaxf(v, lo), hi);
}

// base_grid coordinate: linspace(-1, 1, n)[i]
__device__ __forceinline__ float gridc(int i, int n) {
    return -1.0f + 2.0f * (float)i / (float)(n - 1);
}

// grid_sample single-channel, bilinear, border clamp, align_corners=True
__device__ __forceinline__ float bsamp(const float* __restrict__ p, int Hn, int Wn,
                                       float gy, float gx) {
    float x = clampf((gx + 1.0f) * 0.5f * (float)(Wn - 1), 0.0f, (float)(Wn - 1));
    float y = clampf((gy + 1.0f) * 0.5f * (float)(Hn - 1), 0.0f, (float)(Hn - 1));
    int x0 = (int)floorf(x), y0 = (int)floorf(y);
    int x1 = min(x0 + 1, Wn - 1), y1 = min(y0 + 1, Hn - 1);
    float wx = x - (float)x0, wy = y - (float)y0;
    float v00 = __ldg(p + y0 * Wn + x0);
    float v01 = __ldg(p + y0 * Wn + x1);
    float v10 = __ldg(p + y1 * Wn + x0);
    float v11 = __ldg(p + y1 * Wn + x1);
    return (v00 * (1.0f - wx) + v01 * wx) * (1.0f - wy) +
           (v10 * (1.0f - wx) + v11 * wx) * wy;
}

// same but for interleaved float2 field at half res
__device__ __forceinline__ float2 bsamp2(const float2* __restrict__ p,
                                         float gy, float gx) {
    float x = clampf((gx + 1.0f) * 0.5f * (float)(SW - 1), 0.0f, (float)(SW - 1));
    float y = clampf((gy + 1.0f) * 0.5f * (float)(SH - 1), 0.0f, (float)(SH - 1));
    int x0 = (int)floorf(x), y0 = (int)floorf(y);
    int x1 = min(x0 + 1, SW - 1), y1 = min(y0 + 1, SH - 1);
    float wx = x - (float)x0, wy = y - (float)y0;
    float2 v00 = __ldg(p + y0 * SW + x0);
    float2 v01 = __ldg(p + y0 * SW + x1);
    float2 v10 = __ldg(p + y1 * SW + x0);
    float2 v11 = __ldg(p + y1 * SW + x1);
    float2 r;
    r.x = (v00.x * (1.0f - wx) + v01.x * wx) * (1.0f - wy) +
          (v10.x * (1.0f - wx) + v11.x * wx) * wy;
    r.y = (v00.y * (1.0f - wx) + v01.y * wx) * (1.0f - wy) +
          (v10.y * (1.0f - wx) + v11.y * wx) * wy;
    return r;
}

// ---------------- kernels ----------------

// luma at full res, bilinearly resized to [SH, SW].
// Exact: per-pixel luma is a linear map of channels, bilinear resize is linear,
// so resize(luma(img)) == luma-of-bilinear-taps computed here.
__global__ void k_luma(const float* __restrict__ img, float* __restrict__ out) {
    int idx = blockIdx.x * blockDim.x + threadIdx.x;
    if (idx >= NS) return;
    int j = idx % SW;
    int i = (idx / SW) % SH;
    int b = idx / (SH * SW);

    float gy = gridc(i, SH), gx = gridc(j, SW);
    float x = clampf((gx + 1.0f) * 0.5f * (float)(WW - 1), 0.0f, (float)(WW - 1));
    float y = clampf((gy + 1.0f) * 0.5f * (float)(HH - 1), 0.0f, (float)(HH - 1));
    int x0 = (int)floorf(x), y0 = (int)floorf(y);
    int x1 = min(x0 + 1, WW - 1), y1 = min(y0 + 1, HH - 1);
    float wx = x - (float)x0, wy = y - (float)y0;

    const float* p0 = img + (size_t)(b * 3 + 0) * HH * WW;
    const float* p1 = img + (size_t)(b * 3 + 1) * HH * WW;
    const float* p2 = img + (size_t)(b * 3 + 2) * HH * WW;

    auto lum = [&](int yy, int xx) -> float {
        int o = yy * WW + xx;
        return 0.299f * __ldg(p0 + o) + 0.587f * __ldg(p1 + o) + 0.114f * __ldg(p2 + o);
    };
    float v = (lum(y0, x0) * (1.0f - wx) + lum(y0, x1) * wx) * (1.0f - wy) +
              (lum(y1, x0) * (1.0f - wx) + lum(y1, x1) * wx) * wy;
    out[idx] = v;
}

// sobel_x / kernel_x: src 1ch [B,SH,SW] -> dst 2ch planar
__global__ void k_sobelx(const float* __restrict__ src, float* __restrict__ dst,
                         float offset) {
    int idx = blockIdx.x * blockDim.x + threadIdx.x;
    if (idx >= NS) return;
    int j = idx % SW;
    int i = (idx / SW) % SH;
    int b = idx / (SH * SW);

    float gy = gridc(i, SH), gx = gridc(j, SW);
    float s = 2.0f * offset / (float)SW;  // normalized ddx

    const float* sp = src + (size_t)b * SH * SW;
    float l = bsamp(sp, SH, SW, gy, gx - s);
    float r = bsamp(sp, SH, SW, gy, gx + s);
    float m = sp[i * SW + j];

    float* d0 = dst + (size_t)(b * 2 + 0) * SH * SW;
    float* d1 = dst + (size_t)(b * 2 + 1) * SH * SW;
    d0[i * SW + j] = -l + r;
    d1[i * SW + j] = l + 2.0f * m + r;
}

// sobel_y magnitude: src 2ch planar -> 1ch  (edge = |grad|^0.7)
__global__ void k_sobely_mag(const float* __restrict__ src, float* __restrict__ dst,
                             float offset) {
    int idx = blockIdx.x * blockDim.x + threadIdx.x;
    if (idx >= NS) return;
    int j = idx % SW;
    int i = (idx / SW) % SH;
    int b = idx / (SH * SW);

    float gy = gridc(i, SH), gx = gridc(j, SW);
    float s = 2.0f * offset / (float)SH;  // normalized ddy

    const float* c0 = src + (size_t)(b * 2 + 0) * SH * SW;
    const float* c1 = src + (size_t)(b * 2 + 1) * SH * SW;
    float t0 = bsamp(c0, SH, SW, gy - s, gx);
    float b0 = bsamp(c0, SH, SW, gy + s, gx);
    float t1 = bsamp(c1, SH, SW, gy - s, gx);
    float b1 = bsamp(c1, SH, SW, gy + s, gx);
    float m0 = c0[i * SW + j];

    float xg = (t0 + 2.0f * m0 + b0) * 0.125f;
    float yg = (-t1 + b1) * 0.125f;
    dst[(size_t)b * SH * SW + i * SW + j] = powf(sqrtf(xg * xg + yg * yg), 0.7f);
}

// kernel_y: src 2ch planar -> interleaved float2 grad field
__global__ void k_sobely_vec(const float* __restrict__ src, float2* __restrict__ dst,
                             float offset) {
    int idx = blockIdx.x * blockDim.x + threadIdx.x;
    if (idx >= NS) return;
    int j = idx % SW;
    int i = (idx / SW) % SH;
    int b = idx / (SH * SW);

    float gy = gridc(i, SH), gx = gridc(j, SW);
    float s = 2.0f * offset / (float)SH;

    const float* c0 = src + (size_t)(b * 2 + 0) * SH * SW;
    const float* c1 = src + (size_t)(b * 2 + 1) * SH * SW;
    float t0 = bsamp(c0, SH, SW, gy - s, gx);
    float b0 = bsamp(c0, SH, SW, gy + s, gx);
    float t1 = bsamp(c1, SH, SW, gy - s, gx);
    float b1 = bsamp(c1, SH, SW, gy + s, gx);
    float m0 = c0[i * SW + j];

    dst[idx] = make_float2((t0 + 2.0f * m0 + b0) * 0.125f, (-t1 + b1) * 0.125f);
}

// Fused separable gaussian blur, sigma=1 -> ks=5, radius 2, edge replicate.
#define BTX 32
#define BTY 8
#define RAD 2
__global__ void k_blur(const float* __restrict__ src, float* __restrict__ dst) {
    __shared__ float s_raw[BTY + 2 * RAD][BTX + 2 * RAD];
    __shared__ float s_h  [BTY + 2 * RAD][BTX];

    int b  = blockIdx.z;
    int j0 = blockIdx.x * BTX;
    int i0 = blockIdx.y * BTY;
    const float* sp = src + (size_t)b * SH * SW;

    const float k2 = 0.13533528323661270f;   // exp(-2)
    const float k1 = 0.60653065971263342f;   // exp(-0.5)
    const float sum = 2.0f * k2 + 2.0f * k1 + 1.0f;
    const float w0 = k2 / sum, w1 = k1 / sum, w2 = 1.0f / sum;

    int tid = threadIdx.y * BTX + threadIdx.x;
    const int NT = BTX * BTY;
    const int TOT = (BTY + 2 * RAD) * (BTX + 2 * RAD);
    for (int t = tid; t < TOT; t += NT) {
        int rr = t / (BTX + 2 * RAD);
        int cc = t % (BTX + 2 * RAD);
        int gi = min(max(i0 + rr - RAD, 0), SH - 1);
        int gj = min(max(j0 + cc - RAD, 0), SW - 1);
        s_raw[rr][cc] = __ldg(sp + gi * SW + gj);
    }
    __syncthreads();

    const int TOTH = (BTY + 2 * RAD) * BTX;
    for (int t = tid; t < TOTH; t += NT) {
        int rr = t / BTX;
        int cc = t % BTX;
        s_h[rr][cc] = w0 * (s_raw[rr][cc] + s_raw[rr][cc + 4]) +
                      w1 * (s_raw[rr][cc + 1] + s_raw[rr][cc + 3]) +
                      w2 * s_raw[rr][cc + 2];
    }
    __syncthreads();

    int gi = i0 + threadIdx.y;   // SH=540 not divisible by BTY=8 -> keep guard
    int gj = j0 + threadIdx.x;
    if (gi < SH && gj < SW) {
        int rr = threadIdx.y, cc = threadIdx.x;
        dst[(size_t)b * SH * SW + gi * SW + gj] =
            w0 * (s_h[rr][cc] + s_h[rr + 4][cc]) +
            w1 * (s_h[rr + 1][cc] + s_h[rr + 3][cc]) +
            w2 * s_h[rr + 2][cc];
    }
}

// ---------------- fused upsample + iterative warp + final sample ----------------
// Drift bound: per iteration |delta_pos| = (|dn|/(|dn|+0.01)) * 0.1 px < 0.1 px,
// 6 iterations < 0.6 px total. Bilinear taps therefore hit full-res grad indices
// in [x-1, x+1] worst case; the smem tile holds a +-2 halo (1 px of slack).
// Tile entries are computed with the exact standalone-upsample formula, so the
// fused path is bitwise-equal to the unfused (materialize-gfull) path.
#define WTX 32
#define WTY 8
#define GHALO 2
#define GTW (WTX + 2 * GHALO + 2)   // 36
#define GTH (WTY + 2 * GHALO + 2)   // 12

__global__ void k_warp(const float* __restrict__ img, const float2* __restrict__ grad,
                       float* __restrict__ out) {
    __shared__ float2 s_g[GTH][GTW];

    int b  = blockIdx.z;
    int x0b = blockIdx.x * WTX;
    int y0b = blockIdx.y * WTY;

    const float2* gp = grad + (size_t)b * SH * SW;

    // cooperative tile fill: full-res grad values (bilinear upsample of half-res)
    int tid = threadIdx.y * WTX + threadIdx.x;
    const int NT = WTX * WTY;
    for (int t = tid; t < GTH * GTW; t += NT) {
        int rr = t / GTW, cc = t % GTW;
        int xi = min(max(x0b - GHALO + cc, 0), WW - 1);
        int yi = min(max(y0b - GHALO + rr, 0), HH - 1);
        s_g[rr][cc] = bsamp2(gp, gridc(yi, HH), gridc(xi, WW));
    }
    __syncthreads();

    // 1920 % 32 == 0 and 1080 % 8 == 0: no bounds guard needed
    int x = x0b + threadIdx.x;
    int y = y0b + threadIdx.y;

    float px = gridc(x, WW);
    float py = gridc(y, HH);

    const float relstr = ((float)HH / 1080.0f) * 0.1f;
    const float stepx = (2.0f / (float)WW) * relstr;
    const float stepy = (2.0f / (float)HH) * relstr;

    const int ox = x0b - GHALO;
    const int oy = y0b - GHALO;

    #pragma unroll
    for (int it = 0; it < 6; it++) {
        float xs = clampf((px + 1.0f) * 0.5f * (float)(WW - 1), 0.0f, (float)(WW - 1));
        float ys = clampf((py + 1.0f) * 0.5f * (float)(HH - 1), 0.0f, (float)(HH - 1));
        int x0 = (int)floorf(xs), y0 = (int)floorf(ys);
        int x1 = min(x0 + 1, WW - 1), y1 = min(y0 + 1, HH - 1);
        float wx = xs - (float)x0, wy = ys - (float)y0;

        float2 v00 = s_g[y0 - oy][x0 - ox];
        float2 v01 = s_g[y0 - oy][x1 - ox];
        float2 v10 = s_g[y1 - oy][x0 - ox];
        float2 v11 = s_g[y1 - oy][x1 - ox];
        float dx = (v00.x * (1.0f - wx) + v01.x * wx) * (1.0f - wy) +
                   (v10.x * (1.0f - wx) + v11.x * wx) * wy;
        float dy = (v00.y * (1.0f - wx) + v01.y * wx) * (1.0f - wy) +
                   (v10.y * (1.0f - wx) + v11.y * wx) * wy;
        float len = sqrtf(dx * dx + dy * dy) + 0.01f;
        px -= dx / len * stepx;
        py -= dy / len * stepy;
    }

    // final image sample (3 channels share coordinates) + clip
    float xs = clampf((px + 1.0f) * 0.5f * (float)(WW - 1), 0.0f, (float)(WW - 1));
    float ys = clampf((py + 1.0f) * 0.5f * (float)(HH - 1), 0.0f, (float)(HH - 1));
    int x0 = (int)floorf(xs), y0 = (int)floorf(ys);
    int x1 = min(x0 + 1, WW - 1), y1 = min(y0 + 1, HH - 1);
    float wx = xs - (float)x0, wy = ys - (float)y0;

    #pragma unroll
    for (int c = 0; c < 3; c++) {
        const float* p = img + (size_t)(b * 3 + c) * HH * WW;
        float v00 = __ldg(p + y0 * WW + x0);
        float v01 = __ldg(p + y0 * WW + x1);
        float v10 = __ldg(p + y1 * WW + x0);
        float v11 = __ldg(p + y1 * WW + x1);
        float v = (v00 * (1.0f - wx) + v01 * wx) * (1.0f - wy) +
                  (v10 * (1.0f - wx) + v11 * wx) * wy;
        out[((size_t)(b * 3 + c) * HH + y) * WW + x] = clampf(v, 0.0f, 1.0f);
    }
}

// ---------------- launch ----------------
extern "C" void kernel_launch(void* const* d_in, const int* in_sizes, int n_in,
                              void* d_out, int out_size) {
    const float* img = (const float*)d_in[0];
    float* out = (float*)d_out;

    float *luma, *sxy, *edge, *edge2, *kxy;
    float2* grad;
    cudaGetSymbolAddress((void**)&luma,  g_luma);
    cudaGetSymbolAddress((void**)&sxy,   g_sxy);
    cudaGetSymbolAddress((void**)&edge,  g_edge);
    cudaGetSymbolAddress((void**)&edge2, g_edge2);
    cudaGetSymbolAddress((void**)&kxy,   g_kxy);
    cudaGetSymbolAddress((void**)&grad,  g_grad);

    const int T = 256;
    const int gS = (NS + T - 1) / T;

    k_luma<<<gS, T>>>(img, luma);
    k_sobelx<<<gS, T>>>(luma, sxy, 1.0f);
    k_sobely_mag<<<gS, T>>>(sxy, edge, 1.0f);

    dim3 bt(BTX, BTY);
    dim3 gb((SW + BTX - 1) / BTX, (SH + BTY - 1) / BTY, BB);
    k_blur<<<gb, bt>>>(edge, edge2);

    k_sobelx<<<gS, T>>>(edge2, kxy, 0.5f);
    k_sobely_vec<<<gS, T>>>(kxy, grad, 0.5f);

    dim3 wt(WTX, WTY);
    dim3 gw(WW / WTX, HH / WTY, BB);
    k_warp<<<gw, wt>>>(img, grad, out);
}

// round 7
// speedup vs baseline: 1.5121x; 1.5121x over previous
#include <cuda_runtime.h>
#include <math.h>

// Fixed problem shape: image [2, 3, 1080, 1920] float32
#define BB 2
#define HH 1080
#define WW 1920
#define SH 540
#define SW 960
#define NS (BB * SH * SW)

// ---------------- scratch ----------------
__device__ float  g_edge[NS];
__device__ float2 g_grad[NS];   // half-res grad field, interleaved (xg, yg)

// Constant fractional pixel shifts: offset*(N-1)/N per shift_sample derivation.
#define D1X (959.0f / 960.0f)     // sobel offset 1.0, x
#define D1Y (539.0f / 540.0f)     // sobel offset 1.0, y
#define D2X (959.0f / 1920.0f)    // kernel offset 0.5, x
#define D2Y (539.0f / 1080.0f)    // kernel offset 0.5, y

__device__ __forceinline__ float clampf(float v, float lo, float hi) {
    return fminf(fmaxf(v, lo), hi);
}
__device__ __forceinline__ float gridc(int i, int n) {
    return -1.0f + 2.0f * (float)i / (float)(n - 1);
}
__device__ __forceinline__ int iclamp(int v, int lo, int hi) {
    return min(max(v, lo), hi);
}

// luma of full-res image bilinearly resized to small-res pixel (i, j).
__device__ __forceinline__ float luma_at(const float* __restrict__ img, int b,
                                         int i, int j) {
    float gy = gridc(i, SH), gx = gridc(j, SW);
    float x = clampf((gx + 1.0f) * 0.5f * (float)(WW - 1), 0.0f, (float)(WW - 1));
    float y = clampf((gy + 1.0f) * 0.5f * (float)(HH - 1), 0.0f, (float)(HH - 1));
    int x0 = (int)floorf(x), y0 = (int)floorf(y);
    int x1 = min(x0 + 1, WW - 1), y1 = min(y0 + 1, HH - 1);
    float wx = x - (float)x0, wy = y - (float)y0;

    const float* p0 = img + (size_t)(b * 3 + 0) * HH * WW;
    const float* p1 = img + (size_t)(b * 3 + 1) * HH * WW;
    const float* p2 = img + (size_t)(b * 3 + 2) * HH * WW;
    auto lum = [&](int yy, int xx) -> float {
        int o = yy * WW + xx;
        return 0.299f * __ldg(p0 + o) + 0.587f * __ldg(p1 + o) + 0.114f * __ldg(p2 + o);
    };
    return (lum(y0, x0) * (1.0f - wx) + lum(y0, x1) * wx) * (1.0f - wy) +
           (lum(y1, x0) * (1.0f - wx) + lum(y1, x1) * wx) * wy;
}

// ================= K1: img -> edge  (luma + sobelX(1.0) + sobelY-mag) =========
#define TX 32
#define TY 16
__global__ void k_edge(const float* __restrict__ img, float* __restrict__ edge) {
    __shared__ float L [TY + 2][TX + 2];   // luma tile, halo 1 (clamp-loaded)
    __shared__ float S0[TY + 2][TX];       // sobelX ch0 (-l + r)
    __shared__ float S1[TY + 2][TX];       // sobelX ch1 (l + 2m + r)

    int b   = blockIdx.z;
    int gj0 = blockIdx.x * TX;
    int gi0 = blockIdx.y * TY;
    int tx = threadIdx.x, ty = threadIdx.y;
    int tid = ty * TX + tx;

    for (int t = tid; t < (TY + 2) * (TX + 2); t += TX * TY) {
        int r = t / (TX + 2), c = t % (TX + 2);
        L[r][c] = luma_at(img, b, iclamp(gi0 - 1 + r, 0, SH - 1),
                                  iclamp(gj0 - 1 + c, 0, SW - 1));
    }
    __syncthreads();

    // sobelX: l = d*L[j-1] + (1-d)*L[j]; r = (1-d)*L[j] + d*L[j+1].
    // Clamp-loaded halo reproduces reference border clamping exactly
    // (both taps collapse onto the border texel).
    for (int t = tid; t < (TY + 2) * TX; t += TX * TY) {
        int r = t / TX, c = t % TX;
        float l  = D1X * L[r][c]     + (1.0f - D1X) * L[r][c + 1];
        float rr = (1.0f - D1X) * L[r][c + 1] + D1X * L[r][c + 2];
        S0[r][c] = rr - l;
        S1[r][c] = l + 2.0f * L[r][c + 1] + rr;
    }
    __syncthreads();

    int gi = gi0 + ty;
    if (gi >= SH) return;

    float t0 = D1Y * S0[ty][tx]     + (1.0f - D1Y) * S0[ty + 1][tx];
    float b0 = (1.0f - D1Y) * S0[ty + 1][tx] + D1Y * S0[ty + 2][tx];
    float t1 = D1Y * S1[ty][tx]     + (1.0f - D1Y) * S1[ty + 1][tx];
    float b1 = (1.0f - D1Y) * S1[ty + 1][tx] + D1Y * S1[ty + 2][tx];
    float xg = (t0 + 2.0f * S0[ty + 1][tx] + b0) * 0.125f;
    float yg = (-t1 + b1) * 0.125f;
    edge[(size_t)b * SH * SW + gi * SW + gj0 + tx] =
        __powf(sqrtf(xg * xg + yg * yg), 0.7f);
}

// ========== K2: edge -> grad  (gaussian blur + kernelX(0.5) + kernelY(0.5)) ===
__global__ void k_grad(const float* __restrict__ edge, float2* __restrict__ grad) {
    __shared__ float E  [TY + 6][TX + 6];  // edge tile, halo 3 (clamp-loaded)
    __shared__ float Bh [TY + 6][TX + 2];  // h-blurred, cols = global gj0-1..gj0+32
    __shared__ float Bv [TY + 2][TX + 2];  // blurred,  rows = global gi0-1..gi0+16
    __shared__ float K0 [TY + 2][TX];      // kernelX ch0
    __shared__ float K1s[TY + 2][TX];      // kernelX ch1

    int b   = blockIdx.z;
    int gj0 = blockIdx.x * TX;
    int gi0 = blockIdx.y * TY;
    int tx = threadIdx.x, ty = threadIdx.y;
    int tid = ty * TX + tx;

    const float k2 = 0.13533528323661270f;   // exp(-2)
    const float k1 = 0.60653065971263342f;   // exp(-0.5)
    const float sum = 2.0f * k2 + 2.0f * k1 + 1.0f;
    const float w0 = k2 / sum, w1 = k1 / sum, w2 = 1.0f / sum;

    const float* sp = edge + (size_t)b * SH * SW;
    for (int t = tid; t < (TY + 6) * (TX + 6); t += TX * TY) {
        int r = t / (TX + 6), c = t % (TX + 6);
        E[r][c] = __ldg(sp + iclamp(gi0 - 3 + r, 0, SH - 1) * SW
                           + iclamp(gj0 - 3 + c, 0, SW - 1));
    }
    __syncthreads();

    // pad mode='edge' == index clamp, so clamp-loaded E is exact for the blur
    for (int t = tid; t < (TY + 6) * (TX + 2); t += TX * TY) {
        int r = t / (TX + 2), c = t % (TX + 2);
        Bh[r][c] = w0 * (E[r][c] + E[r][c + 4]) +
                   w1 * (E[r][c + 1] + E[r][c + 3]) + w2 * E[r][c + 2];
    }
    __syncthreads();

    for (int t = tid; t < (TY + 2) * (TX + 2); t += TX * TY) {
        int r = t / (TX + 2), c = t % (TX + 2);
        Bv[r][c] = w0 * (Bh[r][c] + Bh[r + 4][c]) +
                   w1 * (Bh[r + 1][c] + Bh[r + 3][c]) + w2 * Bh[r + 2][c];
    }
    __syncthreads();

    // kernelX with GLOBAL column clamp: virtual out-of-image blur values in the
    // halo are NOT equal to clamped blur values, so clamp indices here.
    for (int t = tid; t < (TY + 2) * TX; t += TX * TY) {
        int r = t / TX, c = t % TX;
        int gj = gj0 + c;
        int cl = (gj - 1 >= 0)      ? c     : c + 1;  // local col of clamp(gj-1)
        int cr = (gj + 1 <= SW - 1) ? c + 2 : c + 1;  // local col of clamp(gj+1)
        float l  = D2X * Bv[r][cl]  + (1.0f - D2X) * Bv[r][c + 1];
        float rr = (1.0f - D2X) * Bv[r][c + 1] + D2X * Bv[r][cr];
        K0[r][c]  = rr - l;
        K1s[r][c] = l + 2.0f * Bv[r][c + 1] + rr;
    }
    __syncthreads();

    int gi = gi0 + ty;
    if (gi >= SH) return;

    // kernelY with GLOBAL row clamp (same reasoning as columns above).
    int rt = (gi - 1 >= 0)      ? ty     : ty + 1;
    int rb = (gi + 1 <= SH - 1) ? ty + 2 : ty + 1;
    float t0 = D2Y * K0[rt][tx]  + (1.0f - D2Y) * K0[ty + 1][tx];
    float b0 = (1.0f - D2Y) * K0[ty + 1][tx] + D2Y * K0[rb][tx];
    float t1 = D2Y * K1s[rt][tx] + (1.0f - D2Y) * K1s[ty + 1][tx];
    float b1 = (1.0f - D2Y) * K1s[ty + 1][tx] + D2Y * K1s[rb][tx];

    grad[(size_t)b * SH * SW + gi * SW + gj0 + tx] =
        make_float2((t0 + 2.0f * K0[ty + 1][tx] + b0) * 0.125f,
                    (-t1 + b1) * 0.125f);
}

// ===================== fused upsample + iterative warp ========================
// Drift < 0.6 px over 6 iterations; +-2 px halo => all taps stay in-tile, so the
// loop runs in LOCAL pixel coordinates with zero per-iteration conversions.
#define WTX 32
#define WTY 16
#define GTW (WTX + 6)   // 38: left halo 2, right halo 3 (covers x0+1)
#define GTH (WTY + 6)   // 22

__global__ void k_warp(const float* __restrict__ img, const float2* __restrict__ grad,
                       float* __restrict__ out) {
    __shared__ float2 s_g[GTH][GTW];

    int b   = blockIdx.z;
    int x0b = blockIdx.x * WTX;
    int y0b = blockIdx.y * WTY;
    int ox = x0b - 2, oy = y0b - 2;
    int tx = threadIdx.x, ty = threadIdx.y;
    int tid = ty * WTX + tx;

    const float2* gp = grad + (size_t)b * SH * SW;

    // tile fill: full-res grad = bilinear upsample of half-res grad
    // (align_corners map: hx = xi*(SW-1)/(WW-1), hy = yi*(SH-1)/(HH-1))
    const float hxs = 959.0f / 1919.0f;
    const float hys = 539.0f / 1079.0f;
    for (int t = tid; t < GTH * GTW; t += WTX * WTY) {
        int rr = t / GTW, cc = t % GTW;
        int xi = iclamp(ox + cc, 0, WW - 1);
        int yi = iclamp(oy + rr, 0, HH - 1);
        float hx = fminf((float)xi * hxs, (float)(SW - 1));
        float hy = fminf((float)yi * hys, (float)(SH - 1));
        int hx0 = (int)hx, hy0 = (int)hy;
        int hx1 = min(hx0 + 1, SW - 1), hy1 = min(hy0 + 1, SH - 1);
        float wx = hx - (float)hx0, wy = hy - (float)hy0;
        float2 v00 = __ldg(gp + hy0 * SW + hx0);
        float2 v01 = __ldg(gp + hy0 * SW + hx1);
        float2 v10 = __ldg(gp + hy1 * SW + hx0);
        float2 v11 = __ldg(gp + hy1 * SW + hx1);
        float2 r;
        r.x = (v00.x * (1.0f - wx) + v01.x * wx) * (1.0f - wy) +
              (v10.x * (1.0f - wx) + v11.x * wx) * wy;
        r.y = (v00.y * (1.0f - wx) + v01.y * wx) * (1.0f - wy) +
              (v10.y * (1.0f - wx) + v11.y * wx) * wy;
        s_g[rr][cc] = r;
    }
    __syncthreads();

    int y = y0b + ty;
    if (y >= HH) return;
    int x = x0b + tx;

    // local pixel coordinates (global - ox/oy); pos accumulates UNclamped,
    // clamped copies used for sampling (matches reference semantics).
    float xl = (float)(tx + 2);
    float yl = (float)(ty + 2);
    const float xlo = (float)(-ox), xhi = (float)(WW - 1 - ox);
    const float ylo = (float)(-oy), yhi = (float)(HH - 1 - oy);
    const float SPX = 0.1f * 1919.0f / 1920.0f;  // step in pixel units
    const float SPY = 0.1f * 1079.0f / 1080.0f;

    #pragma unroll
    for (int it = 0; it < 6; it++) {
        float xc = clampf(xl, xlo, xhi);
        float yc = clampf(yl, ylo, yhi);
        int x0i = (int)xc, y0i = (int)yc;     // xc,yc >= 0: cast == floor
        float wx = xc - (float)x0i, wy = yc - (float)y0i;
        const float2* base = &s_g[y0i][x0i];
        float2 v00 = base[0], v01 = base[1], v10 = base[GTW], v11 = base[GTW + 1];
        float dx = (v00.x * (1.0f - wx) + v01.x * wx) * (1.0f - wy) +
                   (v10.x * (1.0f - wx) + v11.x * wx) * wy;
        float dy = (v00.y * (1.0f - wx) + v01.y * wx) * (1.0f - wy) +
                   (v10.y * (1.0f - wx) + v11.y * wx) * wy;
        float f = __fdividef(1.0f, sqrtf(dx * dx + dy * dy) + 0.01f);
        xl -= dx * f * SPX;
        yl -= dy * f * SPY;
    }

    // final image sample in global coordinates + clip
    float xs = clampf(xl + (float)ox, 0.0f, (float)(WW - 1));
    float ys = clampf(yl + (float)oy, 0.0f, (float)(HH - 1));
    int x0 = (int)xs, y0 = (int)ys;
    int x1 = min(x0 + 1, WW - 1), y1 = min(y0 + 1, HH - 1);
    float wx = xs - (float)x0, wy = ys - (float)y0;

    #pragma unroll
    for (int c = 0; c < 3; c++) {
        const float* p = img + (size_t)(b * 3 + c) * HH * WW;
        float v00 = __ldg(p + y0 * WW + x0);
        float v01 = __ldg(p + y0 * WW + x1);
        float v10 = __ldg(p + y1 * WW + x0);
        float v11 = __ldg(p + y1 * WW + x1);
        float v = (v00 * (1.0f - wx) + v01 * wx) * (1.0f - wy) +
                  (v10 * (1.0f - wx) + v11 * wx) * wy;
        out[((size_t)(b * 3 + c) * HH + y) * WW + x] = clampf(v, 0.0f, 1.0f);
    }
}

// ---------------- launch ----------------
extern "C" void kernel_launch(void* const* d_in, const int* in_sizes, int n_in,
                              void* d_out, int out_size) {
    const float* img = (const float*)d_in[0];
    float* out = (float*)d_out;

    float* edge;
    float2* grad;
    cudaGetSymbolAddress((void**)&edge, g_edge);
    cudaGetSymbolAddress((void**)&grad, g_grad);

    dim3 bt(TX, TY);
    dim3 gs(SW / TX, (SH + TY - 1) / TY, BB);        // 30 x 34 x 2
    k_edge<<<gs, bt>>>(img, edge);
    k_grad<<<gs, bt>>>(edge, grad);

    dim3 wt(WTX, WTY);
    dim3 gw(WW / WTX, (HH + WTY - 1) / WTY, BB);     // 60 x 68 x 2
    k_warp<<<gw, wt>>>(img, grad, out);
}

// round 9
// speedup vs baseline: 1.5455x; 1.0221x over previous
#include <cuda_runtime.h>
#include <math.h>

// Fixed problem shape: image [2, 3, 1080, 1920] float32
#define BB 2
#define HH 1080
#define WW 1920
#define SH 540
#define SW 960
#define NS (BB * SH * SW)

// ---------------- scratch ----------------
__device__ float  g_edge[NS];
__device__ float2 g_grad[NS];   // half-res grad field, interleaved (xg, yg)

// Constant fractional pixel shifts: offset*(N-1)/N per shift_sample derivation.
#define D1X (959.0f / 960.0f)     // sobel offset 1.0, x
#define D1Y (539.0f / 540.0f)     // sobel offset 1.0, y
#define D2X (959.0f / 1920.0f)    // kernel offset 0.5, x
#define D2Y (539.0f / 1080.0f)    // kernel offset 0.5, y

__device__ __forceinline__ float clampf(float v, float lo, float hi) {
    return fminf(fmaxf(v, lo), hi);
}
__device__ __forceinline__ float gridc(int i, int n) {
    return -1.0f + 2.0f * (float)i / (float)(n - 1);
}
__device__ __forceinline__ int iclamp(int v, int lo, int hi) {
    return min(max(v, lo), hi);
}

// luma of full-res image bilinearly resized to small-res pixel (i, j).
__device__ __forceinline__ float luma_at(const float* __restrict__ img, int b,
                                         int i, int j) {
    float gy = gridc(i, SH), gx = gridc(j, SW);
    float x = clampf((gx + 1.0f) * 0.5f * (float)(WW - 1), 0.0f, (float)(WW - 1));
    float y = clampf((gy + 1.0f) * 0.5f * (float)(HH - 1), 0.0f, (float)(HH - 1));
    int x0 = (int)floorf(x), y0 = (int)floorf(y);
    int x1 = min(x0 + 1, WW - 1), y1 = min(y0 + 1, HH - 1);
    float wx = x - (float)x0, wy = y - (float)y0;

    const float* p0 = img + (size_t)(b * 3 + 0) * HH * WW;
    const float* p1 = img + (size_t)(b * 3 + 1) * HH * WW;
    const float* p2 = img + (size_t)(b * 3 + 2) * HH * WW;
    auto lum = [&](int yy, int xx) -> float {
        int o = yy * WW + xx;
        return 0.299f * __ldg(p0 + o) + 0.587f * __ldg(p1 + o) + 0.114f * __ldg(p2 + o);
    };
    return (lum(y0, x0) * (1.0f - wx) + lum(y0, x1) * wx) * (1.0f - wy) +
           (lum(y1, x0) * (1.0f - wx) + lum(y1, x1) * wx) * wy;
}

// ================= K1: img -> edge  (luma + sobelX(1.0) + sobelY-mag) =========
#define TX 32
#define TY 16
__global__ void k_edge(const float* __restrict__ img, float* __restrict__ edge) {
    __shared__ float L [TY + 2][TX + 2];   // luma tile, halo 1 (clamp-loaded)
    __shared__ float S0[TY + 2][TX];       // sobelX ch0 (-l + r)
    __shared__ float S1[TY + 2][TX];       // sobelX ch1 (l + 2m + r)

    int b   = blockIdx.z;
    int gj0 = blockIdx.x * TX;
    int gi0 = blockIdx.y * TY;
    int tx = threadIdx.x, ty = threadIdx.y;
    int tid = ty * TX + tx;

    for (int t = tid; t < (TY + 2) * (TX + 2); t += TX * TY) {
        int r = t / (TX + 2), c = t % (TX + 2);
        L[r][c] = luma_at(img, b, iclamp(gi0 - 1 + r, 0, SH - 1),
                                  iclamp(gj0 - 1 + c, 0, SW - 1));
    }
    __syncthreads();

    // sobelX: clamp-loaded halo reproduces reference border clamping exactly.
    for (int t = tid; t < (TY + 2) * TX; t += TX * TY) {
        int r = t / TX, c = t % TX;
        float l  = D1X * L[r][c]     + (1.0f - D1X) * L[r][c + 1];
        float rr = (1.0f - D1X) * L[r][c + 1] + D1X * L[r][c + 2];
        S0[r][c] = rr - l;
        S1[r][c] = l + 2.0f * L[r][c + 1] + rr;
    }
    __syncthreads();

    int gi = gi0 + ty;
    if (gi >= SH) return;

    float t0 = D1Y * S0[ty][tx]     + (1.0f - D1Y) * S0[ty + 1][tx];
    float b0 = (1.0f - D1Y) * S0[ty + 1][tx] + D1Y * S0[ty + 2][tx];
    float t1 = D1Y * S1[ty][tx]     + (1.0f - D1Y) * S1[ty + 1][tx];
    float b1 = (1.0f - D1Y) * S1[ty + 1][tx] + D1Y * S1[ty + 2][tx];
    float xg = (t0 + 2.0f * S0[ty + 1][tx] + b0) * 0.125f;
    float yg = (-t1 + b1) * 0.125f;
    edge[(size_t)b * SH * SW + gi * SW + gj0 + tx] =
        __powf(sqrtf(xg * xg + yg * yg), 0.7f);
}

// ========== K2: edge -> grad  (gaussian blur + kernelX(0.5) + kernelY(0.5)) ===
__global__ void k_grad(const float* __restrict__ edge, float2* __restrict__ grad) {
    __shared__ float E  [TY + 6][TX + 6];  // edge tile, halo 3 (clamp-loaded)
    __shared__ float Bh [TY + 6][TX + 2];
    __shared__ float Bv [TY + 2][TX + 2];
    __shared__ float K0 [TY + 2][TX];
    __shared__ float K1s[TY + 2][TX];

    int b   = blockIdx.z;
    int gj0 = blockIdx.x * TX;
    int gi0 = blockIdx.y * TY;
    int tx = threadIdx.x, ty = threadIdx.y;
    int tid = ty * TX + tx;

    const float k2 = 0.13533528323661270f;   // exp(-2)
    const float k1 = 0.60653065971263342f;   // exp(-0.5)
    const float sum = 2.0f * k2 + 2.0f * k1 + 1.0f;
    const float w0 = k2 / sum, w1 = k1 / sum, w2 = 1.0f / sum;

    const float* sp = edge + (size_t)b * SH * SW;
    for (int t = tid; t < (TY + 6) * (TX + 6); t += TX * TY) {
        int r = t / (TX + 6), c = t % (TX + 6);
        E[r][c] = __ldg(sp + iclamp(gi0 - 3 + r, 0, SH - 1) * SW
                           + iclamp(gj0 - 3 + c, 0, SW - 1));
    }
    __syncthreads();

    for (int t = tid; t < (TY + 6) * (TX + 2); t += TX * TY) {
        int r = t / (TX + 2), c = t % (TX + 2);
        Bh[r][c] = w0 * (E[r][c] + E[r][c + 4]) +
                   w1 * (E[r][c + 1] + E[r][c + 3]) + w2 * E[r][c + 2];
    }
    __syncthreads();

    for (int t = tid; t < (TY + 2) * (TX + 2); t += TX * TY) {
        int r = t / (TX + 2), c = t % (TX + 2);
        Bv[r][c] = w0 * (Bh[r][c] + Bh[r + 4][c]) +
                   w1 * (Bh[r + 1][c] + Bh[r + 3][c]) + w2 * Bh[r + 2][c];
    }
    __syncthreads();

    // kernelX with GLOBAL column clamp (halo blur values != clamped values).
    for (int t = tid; t < (TY + 2) * TX; t += TX * TY) {
        int r = t / TX, c = t % TX;
        int gj = gj0 + c;
        int cl = (gj - 1 >= 0)      ? c     : c + 1;
        int cr = (gj + 1 <= SW - 1) ? c + 2 : c + 1;
        float l  = D2X * Bv[r][cl]  + (1.0f - D2X) * Bv[r][c + 1];
        float rr = (1.0f - D2X) * Bv[r][c + 1] + D2X * Bv[r][cr];
        K0[r][c]  = rr - l;
        K1s[r][c] = l + 2.0f * Bv[r][c + 1] + rr;
    }
    __syncthreads();

    int gi = gi0 + ty;
    if (gi >= SH) return;

    int rt = (gi - 1 >= 0)      ? ty     : ty + 1;
    int rb = (gi + 1 <= SH - 1) ? ty + 2 : ty + 1;
    float t0 = D2Y * K0[rt][tx]  + (1.0f - D2Y) * K0[ty + 1][tx];
    float b0 = (1.0f - D2Y) * K0[ty + 1][tx] + D2Y * K0[rb][tx];
    float t1 = D2Y * K1s[rt][tx] + (1.0f - D2Y) * K1s[ty + 1][tx];
    float b1 = (1.0f - D2Y) * K1s[ty + 1][tx] + D2Y * K1s[rb][tx];

    grad[(size_t)b * SH * SW + gi * SW + gj0 + tx] =
        make_float2((t0 + 2.0f * K0[ty + 1][tx] + b0) * 0.125f,
                    (-t1 + b1) * 0.125f);
}

// ===================== fused upsample + iterative warp ========================
// Drift < 0.6 px over 6 iterations => taps span [x-1, x+1]: halo 1 suffices.
// 2 output pixels per thread (rows ty and ty+8): two independent iteration
// chains per thread give ILP to cover LDS latency.
#define WTX 32
#define WTY 8            // thread rows; block covers 32 x 16 output pixels
#define TLH 16
#define GTW (WTX + 2)    // 34
#define GTH (TLH + 2)    // 18

__global__ void k_warp(const float* __restrict__ img, const float2* __restrict__ grad,
                       float* __restrict__ out) {
    __shared__ float2 s_g[GTH][GTW];

    int b   = blockIdx.z;
    int x0b = blockIdx.x * WTX;
    int y0b = blockIdx.y * TLH;
    int ox = x0b - 1, oy = y0b - 1;
    int tx = threadIdx.x, ty = threadIdx.y;
    int tid = ty * WTX + tx;

    const float2* gp = grad + (size_t)b * SH * SW;

    // tile fill: full-res grad = bilinear upsample of half-res grad
    // (align_corners map: hx = xi*(SW-1)/(WW-1), hy = yi*(SH-1)/(HH-1))
    const float hxs = 959.0f / 1919.0f;
    const float hys = 539.0f / 1079.0f;
    for (int t = tid; t < GTH * GTW; t += WTX * WTY) {
        int rr = t / GTW, cc = t % GTW;
        int xi = iclamp(ox + cc, 0, WW - 1);
        int yi = iclamp(oy + rr, 0, HH - 1);
        float hx = fminf((float)xi * hxs, (float)(SW - 1));
        float hy = fminf((float)yi * hys, (float)(SH - 1));
        int hx0 = (int)hx, hy0 = (int)hy;
        int hx1 = min(hx0 + 1, SW - 1), hy1 = min(hy0 + 1, SH - 1);
        float wx = hx - (float)hx0, wy = hy - (float)hy0;
        float2 v00 = __ldg(gp + hy0 * SW + hx0);
        float2 v01 = __ldg(gp + hy0 * SW + hx1);
        float2 v10 = __ldg(gp + hy1 * SW + hx0);
        float2 v11 = __ldg(gp + hy1 * SW + hx1);
        float2 r;
        r.x = (v00.x * (1.0f - wx) + v01.x * wx) * (1.0f - wy) +
              (v10.x * (1.0f - wx) + v11.x * wx) * wy;
        r.y = (v00.y * (1.0f - wx) + v01.y * wx) * (1.0f - wy) +
              (v10.y * (1.0f - wx) + v11.y * wx) * wy;
        s_g[rr][cc] = r;
    }
    __syncthreads();

    // local pixel coordinates (global - ox/oy); pos accumulates UNclamped,
    // clamped copies used for sampling (matches reference semantics).
    const float xlo = (float)(-ox), xhi = (float)(WW - 1 - ox);
    const float ylo = (float)(-oy), yhi = (float)(HH - 1 - oy);
    const float SPX = 0.1f * 1919.0f / 1920.0f;  // step in pixel units
    const float SPY = 0.1f * 1079.0f / 1080.0f;

    float xl[2], yl[2];
    xl[0] = (float)(tx + 1);  yl[0] = (float)(ty + 1);
    xl[1] = (float)(tx + 1);  yl[1] = (float)(ty + 9);

    #pragma unroll
    for (int it = 0; it < 6; it++) {
        #pragma unroll
        for (int p = 0; p < 2; p++) {
            float xc = clampf(xl[p], xlo, xhi);
            float yc = clampf(yl[p], ylo, yhi);
            int x0i = (int)xc, y0i = (int)yc;   // xc,yc >= 0: cast == floor
            float wx = xc - (float)x0i, wy = yc - (float)y0i;
            const float2* base = &s_g[y0i][x0i];
            float2 v00 = base[0], v01 = base[1];
            float2 v10 = base[GTW], v11 = base[GTW + 1];
            float dx = (v00.x * (1.0f - wx) + v01.x * wx) * (1.0f - wy) +
                       (v10.x * (1.0f - wx) + v11.x * wx) * wy;
            float dy = (v00.y * (1.0f - wx) + v01.y * wx) * (1.0f - wy) +
                       (v10.y * (1.0f - wx) + v11.y * wx) * wy;
            float f = __fdividef(1.0f, sqrtf(dx * dx + dy * dy) + 0.01f);
            xl[p] -= dx * f * SPX;
            yl[p] -= dy * f * SPY;
        }
    }

    int x = x0b + tx;
    #pragma unroll
    for (int p = 0; p < 2; p++) {
        int y = y0b + ty + p * WTY;
        if (y >= HH) continue;   // only possible for p=1 in last block row

        float xs = clampf(xl[p] + (float)ox, 0.0f, (float)(WW - 1));
        float ys = clampf(yl[p] + (float)oy, 0.0f, (float)(HH - 1));
        int x0 = (int)xs, y0 = (int)ys;
        int x1 = min(x0 + 1, WW - 1), y1 = min(y0 + 1, HH - 1);
        float wx = xs - (float)x0, wy = ys - (float)y0;

        #pragma unroll
        for (int c = 0; c < 3; c++) {
            const float* pp = img + (size_t)(b * 3 + c) * HH * WW;
            float v00 = __ldg(pp + y0 * WW + x0);
            float v01 = __ldg(pp + y0 * WW + x1);
            float v10 = __ldg(pp + y1 * WW + x0);
            float v11 = __ldg(pp + y1 * WW + x1);
            float v = (v00 * (1.0f - wx) + v01 * wx) * (1.0f - wy) +
                      (v10 * (1.0f - wx) + v11 * wx) * wy;
            out[((size_t)(b * 3 + c) * HH + y) * WW + x] = clampf(v, 0.0f, 1.0f);
        }
    }
}

// ---------------- launch ----------------
extern "C" void kernel_launch(void* const* d_in, const int* in_sizes, int n_in,
                              void* d_out, int out_size) {
    const float* img = (const float*)d_in[0];
    float* out = (float*)d_out;

    float* edge;
    float2* grad;
    cudaGetSymbolAddress((void**)&edge, g_edge);
    cudaGetSymbolAddress((void**)&grad, g_grad);

    dim3 bt(TX, TY);
    dim3 gs(SW / TX, (SH + TY - 1) / TY, BB);            // 30 x 34 x 2
    k_edge<<<gs, bt>>>(img, edge);
    k_grad<<<gs, bt>>>(edge, grad);

    dim3 wt(WTX, WTY);                                   // 32 x 8 = 256 threads
    dim3 gw(WW / WTX, (HH + TLH - 1) / TLH, BB);         // 60 x 68 x 2
    k_warp<<<gw, wt>>>(img, grad, out);
}

// round 13
// speedup vs baseline: 1.7053x; 1.1034x over previous
#include <cuda_runtime.h>
#include <math.h>

// Fixed problem shape: image [2, 3, 1080, 1920] float32
#define BB 2
#define HH 1080
#define WW 1920
#define SH 540
#define SW 960
#define NS (BB * SH * SW)

// ---------------- scratch ----------------
__device__ float  g_edge[NS];
__device__ float2 g_grad[NS];   // half-res grad field, interleaved (xg, yg)

// Constant fractional pixel shifts: offset*(N-1)/N per shift_sample derivation.
#define D1X (959.0f / 960.0f)     // sobel offset 1.0, x
#define D1Y (539.0f / 540.0f)     // sobel offset 1.0, y
#define D2X (959.0f / 1920.0f)    // kernel offset 0.5, x
#define D2Y (539.0f / 1080.0f)    // kernel offset 0.5, y

typedef unsigned long long u64;

__device__ __forceinline__ float clampf(float v, float lo, float hi) {
    return fminf(fmaxf(v, lo), hi);
}
__device__ __forceinline__ int iclamp(int v, int lo, int hi) {
    return min(max(v, lo), hi);
}

// ---- packed f32x2 helpers (sm_103a) ----
__device__ __forceinline__ u64 pack2(float lo, float hi) {
    u64 r; asm("mov.b64 %0, {%1, %2};" : "=l"(r) : "f"(lo), "f"(hi)); return r;
}
__device__ __forceinline__ void unpack2(u64 v, float& lo, float& hi) {
    asm("mov.b64 {%0, %1}, %2;" : "=f"(lo), "=f"(hi) : "l"(v));
}
__device__ __forceinline__ u64 mul2(u64 a, u64 b) {
    u64 r; asm("mul.rn.f32x2 %0, %1, %2;" : "=l"(r) : "l"(a), "l"(b)); return r;
}
__device__ __forceinline__ u64 fma2(u64 a, u64 b, u64 c) {
    u64 r; asm("fma.rn.f32x2 %0, %1, %2, %3;" : "=l"(r) : "l"(a), "l"(b), "l"(c)); return r;
}
// bilinear on packed float2 values; weights pre-packed (w broadcast, 1-w broadcast)
__device__ __forceinline__ u64 bilin2(u64 v00, u64 v01, u64 v10, u64 v11,
                                      u64 wx2, u64 ox2, u64 wy2, u64 oy2) {
    u64 top = fma2(v01, wx2, mul2(v00, ox2));
    u64 bot = fma2(v11, wx2, mul2(v10, ox2));
    return fma2(bot, wy2, mul2(top, oy2));
}

// ================= K1: img -> edge  (luma + sobelX(1.0) + sobelY-mag) =========
// Coalesced: stream the full-res 3-channel region into a full-res luma smem
// tile with sequential row reads, then resize from smem. Bilinear is continuous
// in its coordinates, so few-ulp coordinate reassociation is harmless.
#define TX 32
#define TY 16
#define LFH 38    // rows needed <= Y0 + floor(17*1079/539)+1 = Y0+36
#define LFW 70    // cols needed <= X0 + floor(33*1919/959)+1 = X0+68
#define LFWP 72   // padded row stride

__global__ void k_edge(const float* __restrict__ img, float* __restrict__ edge) {
    __shared__ float LF[LFH][LFWP];        // full-res luma region
    __shared__ float L [TY + 2][TX + 2];   // small-res luma (halo 1)
    __shared__ float S0[TY + 2][TX];       // sobelX ch0 (-l + r)
    __shared__ float S1[TY + 2][TX];       // sobelX ch1 (l + 2m + r)

    int b   = blockIdx.z;
    int gj0 = blockIdx.x * TX;
    int gi0 = blockIdx.y * TY;
    int tx = threadIdx.x, ty = threadIdx.y;
    int tid = ty * TX + tx;
    const int NT = TX * TY;  // 512

    const float YS = 1079.0f / 539.0f;   // full-res y per small-res row
    const float XS = 1919.0f / 959.0f;

    int isLo = max(gi0 - 1, 0);
    int jsLo = max(gj0 - 1, 0);
    int Y0 = (int)((float)isLo * YS);    // nonneg: cast == floor
    int X0 = (int)((float)jsLo * XS);

    // stream full-res luma region (rows coalesced; edge clamp on overflow)
    const float* p0 = img + (size_t)(b * 3 + 0) * HH * WW;
    const float* p1 = img + (size_t)(b * 3 + 1) * HH * WW;
    const float* p2 = img + (size_t)(b * 3 + 2) * HH * WW;
    for (int t = tid; t < LFH * LFW; t += NT) {
        int r = t / LFW, c = t % LFW;
        int yi = min(Y0 + r, HH - 1);
        int xi = min(X0 + c, WW - 1);
        int o = yi * WW + xi;
        LF[r][c] = 0.299f * __ldg(p0 + o) + 0.587f * __ldg(p1 + o)
                 + 0.114f * __ldg(p2 + o);
    }
    __syncthreads();

    // small-res luma (halo 1) via bilinear resize from the smem luma region
    for (int t = tid; t < (TY + 2) * (TX + 2); t += NT) {
        int r = t / (TX + 2), c = t % (TX + 2);
        int is = iclamp(gi0 - 1 + r, 0, SH - 1);
        int js = iclamp(gj0 - 1 + c, 0, SW - 1);
        float y = fminf((float)is * YS, (float)(HH - 1));
        float x = fminf((float)js * XS, (float)(WW - 1));
        int y0 = (int)y, x0 = (int)x;
        float wy = y - (float)y0, wx = x - (float)x0;
        int r0 = y0 - Y0, c0 = x0 - X0;
        int r1 = min(y0 + 1, HH - 1) - Y0;
        int c1 = min(x0 + 1, WW - 1) - X0;
        float v00 = LF[r0][c0], v01 = LF[r0][c1];
        float v10 = LF[r1][c0], v11 = LF[r1][c1];
        L[r][c] = (v00 * (1.0f - wx) + v01 * wx) * (1.0f - wy) +
                  (v10 * (1.0f - wx) + v11 * wx) * wy;
    }
    __syncthreads();

    // sobelX: clamp-loaded halo reproduces reference border clamping exactly.
    for (int t = tid; t < (TY + 2) * TX; t += NT) {
        int r = t / TX, c = t % TX;
        float l  = D1X * L[r][c]     + (1.0f - D1X) * L[r][c + 1];
        float rr = (1.0f - D1X) * L[r][c + 1] + D1X * L[r][c + 2];
        S0[r][c] = rr - l;
        S1[r][c] = l + 2.0f * L[r][c + 1] + rr;
    }
    __syncthreads();

    int gi = gi0 + ty;
    if (gi >= SH) return;

    float t0 = D1Y * S0[ty][tx]     + (1.0f - D1Y) * S0[ty + 1][tx];
    float b0 = (1.0f - D1Y) * S0[ty + 1][tx] + D1Y * S0[ty + 2][tx];
    float t1 = D1Y * S1[ty][tx]     + (1.0f - D1Y) * S1[ty + 1][tx];
    float b1 = (1.0f - D1Y) * S1[ty + 1][tx] + D1Y * S1[ty + 2][tx];
    float xg = (t0 + 2.0f * S0[ty + 1][tx] + b0) * 0.125f;
    float yg = (-t1 + b1) * 0.125f;
    edge[(size_t)b * SH * SW + gi * SW + gj0 + tx] =
        __powf(sqrtf(xg * xg + yg * yg), 0.7f);
}

// ========== K2: edge -> grad  (gaussian blur + kernelX(0.5) + kernelY(0.5)) ===
__global__ void k_grad(const float* __restrict__ edge, float2* __restrict__ grad) {
    __shared__ float E  [TY + 6][TX + 6];
    __shared__ float Bh [TY + 6][TX + 2];
    __shared__ float Bv [TY + 2][TX + 2];
    __shared__ float K0 [TY + 2][TX];
    __shared__ float K1s[TY + 2][TX];

    int b   = blockIdx.z;
    int gj0 = blockIdx.x * TX;
    int gi0 = blockIdx.y * TY;
    int tx = threadIdx.x, ty = threadIdx.y;
    int tid = ty * TX + tx;

    const float k2 = 0.13533528323661270f;
    const float k1 = 0.60653065971263342f;
    const float sum = 2.0f * k2 + 2.0f * k1 + 1.0f;
    const float w0 = k2 / sum, w1 = k1 / sum, w2 = 1.0f / sum;

    const float* sp = edge + (size_t)b * SH * SW;
    for (int t = tid; t < (TY + 6) * (TX + 6); t += TX * TY) {
        int r = t / (TX + 6), c = t % (TX + 6);
        E[r][c] = __ldg(sp + iclamp(gi0 - 3 + r, 0, SH - 1) * SW
                           + iclamp(gj0 - 3 + c, 0, SW - 1));
    }
    __syncthreads();

    for (int t = tid; t < (TY + 6) * (TX + 2); t += TX * TY) {
        int r = t / (TX + 2), c = t % (TX + 2);
        Bh[r][c] = w0 * (E[r][c] + E[r][c + 4]) +
                   w1 * (E[r][c + 1] + E[r][c + 3]) + w2 * E[r][c + 2];
    }
    __syncthreads();

    for (int t = tid; t < (TY + 2) * (TX + 2); t += TX * TY) {
        int r = t / (TX + 2), c = t % (TX + 2);
        Bv[r][c] = w0 * (Bh[r][c] + Bh[r + 4][c]) +
                   w1 * (Bh[r + 1][c] + Bh[r + 3][c]) + w2 * Bh[r + 2][c];
    }
    __syncthreads();

    // kernelX with GLOBAL column clamp (halo blur values != clamped values).
    for (int t = tid; t < (TY + 2) * TX; t += TX * TY) {
        int r = t / TX, c = t % TX;
        int gj = gj0 + c;
        int cl = (gj - 1 >= 0)      ? c     : c + 1;
        int cr = (gj + 1 <= SW - 1) ? c + 2 : c + 1;
        float l  = D2X * Bv[r][cl]  + (1.0f - D2X) * Bv[r][c + 1];
        float rr = (1.0f - D2X) * Bv[r][c + 1] + D2X * Bv[r][cr];
        K0[r][c]  = rr - l;
        K1s[r][c] = l + 2.0f * Bv[r][c + 1] + rr;
    }
    __syncthreads();

    int gi = gi0 + ty;
    if (gi >= SH) return;

    int rt = (gi - 1 >= 0)      ? ty     : ty + 1;
    int rb = (gi + 1 <= SH - 1) ? ty + 2 : ty + 1;
    float t0 = D2Y * K0[rt][tx]  + (1.0f - D2Y) * K0[ty + 1][tx];
    float b0 = (1.0f - D2Y) * K0[ty + 1][tx] + D2Y * K0[rb][tx];
    float t1 = D2Y * K1s[rt][tx] + (1.0f - D2Y) * K1s[ty + 1][tx];
    float b1 = (1.0f - D2Y) * K1s[ty + 1][tx] + D2Y * K1s[rb][tx];

    grad[(size_t)b * SH * SW + gi * SW + gj0 + tx] =
        make_float2((t0 + 2.0f * K0[ty + 1][tx] + b0) * 0.125f,
                    (-t1 + b1) * 0.125f);
}

// ===================== fused upsample + iterative warp ========================
#define WTX 32
#define WTY 8            // thread rows; block covers 32 x 16 output pixels
#define TLH 16
#define GTW (WTX + 2)    // 34
#define GTH (TLH + 2)    // 18

__device__ __forceinline__ void step_update(float& xl, float& yl,
                                            float dx, float dy,
                                            float SPX, float SPY) {
    float f = __fdividef(1.0f, sqrtf(dx * dx + dy * dy) + 0.01f);
    xl -= dx * f * SPX;
    yl -= dy * f * SPY;
}

__global__ void k_warp(const float* __restrict__ img, const float2* __restrict__ grad,
                       float* __restrict__ out) {
    __shared__ float2 s_g[GTH][GTW];
    __shared__ float CWX[GTW];  __shared__ int CX0[GTW];
    __shared__ float CWY[GTH];  __shared__ int CY0[GTH];

    int b   = blockIdx.z;
    int x0b = blockIdx.x * WTX;
    int y0b = blockIdx.y * TLH;
    int ox = x0b - 1, oy = y0b - 1;
    int tx = threadIdx.x, ty = threadIdx.y;
    int tid = ty * WTX + tx;
    const int NT = WTX * WTY;  // 256

    const float2* gp = grad + (size_t)b * SH * SW;
    const float hxs = 959.0f / 1919.0f;
    const float hys = 539.0f / 1079.0f;

    // per-column / per-row upsample coefficients
    if (tid < GTW) {
        int xi = iclamp(ox + tid, 0, WW - 1);
        float hx = fminf((float)xi * hxs, (float)(SW - 1));
        int h0 = (int)hx;
        CX0[tid] = h0; CWX[tid] = hx - (float)h0;
    } else if (tid < GTW + GTH) {
        int k = tid - GTW;
        int yi = iclamp(oy + k, 0, HH - 1);
        float hy = fminf((float)yi * hys, (float)(SH - 1));
        int h0 = (int)hy;
        CY0[k] = h0; CWY[k] = hy - (float)h0;
    }
    __syncthreads();

    // tile fill: full-res grad = bilinear upsample of half-res grad (f32x2)
    for (int t = tid; t < GTH * GTW; t += NT) {
        int r = t / GTW, c = t % GTW;
        int hx0 = CX0[c], hy0 = CY0[r];
        float wx = CWX[c], wy = CWY[r];
        int hx1 = min(hx0 + 1, SW - 1), hy1 = min(hy0 + 1, SH - 1);
        const u64* row0 = (const u64*)(gp + hy0 * SW);
        const u64* row1 = (const u64*)(gp + hy1 * SW);
        u64 v00 = __ldg(row0 + hx0), v01 = __ldg(row0 + hx1);
        u64 v10 = __ldg(row1 + hx0), v11 = __ldg(row1 + hx1);
        u64 wx2 = pack2(wx, wx), ox2 = pack2(1.0f - wx, 1.0f - wx);
        u64 wy2 = pack2(wy, wy), oy2 = pack2(1.0f - wy, 1.0f - wy);
        *(u64*)&s_g[r][c] = bilin2(v00, v01, v10, v11, wx2, ox2, wy2, oy2);
    }
    __syncthreads();

    // local pixel coordinates; pos accumulates UNclamped, clamped copies sample.
    const float xlo = (float)(-ox), xhi = (float)(WW - 1 - ox);
    const float ylo = (float)(-oy), yhi = (float)(HH - 1 - oy);
    const float SPX = 0.1f * 1919.0f / 1920.0f;
    const float SPY = 0.1f * 1079.0f / 1080.0f;

    float xl[2], yl[2];
    xl[0] = (float)(tx + 1);  yl[0] = (float)(ty + 1);
    xl[1] = (float)(tx + 1);  yl[1] = (float)(ty + 9);

    // iteration 1: start pos is exactly a texel (integral coords, clamp no-op,
    // wx=wy=0) -> bilinear degenerates to a single direct read. Exact.
    {
        float2 ga = s_g[ty + 1][tx + 1];
        float2 gb = s_g[ty + 9][tx + 1];
        step_update(xl[0], yl[0], ga.x, ga.y, SPX, SPY);
        step_update(xl[1], yl[1], gb.x, gb.y, SPX, SPY);
    }

    // iterations 2..6: general bilinear (f32x2), 2 independent chains
    #pragma unroll
    for (int it = 0; it < 5; it++) {
        #pragma unroll
        for (int p = 0; p < 2; p++) {
            float xc = clampf(xl[p], xlo, xhi);
            float yc = clampf(yl[p], ylo, yhi);
            int x0i = (int)xc, y0i = (int)yc;   // nonneg: cast == floor
            float wx = xc - (float)x0i, wy = yc - (float)y0i;
            const u64* base = (const u64*)&s_g[y0i][x0i];
            u64 v00 = base[0], v01 = base[1];
            u64 v10 = base[GTW], v11 = base[GTW + 1];
            u64 wx2 = pack2(wx, wx), ox2 = pack2(1.0f - wx, 1.0f - wx);
            u64 wy2 = pack2(wy, wy), oy2 = pack2(1.0f - wy, 1.0f - wy);
            u64 res = bilin2(v00, v01, v10, v11, wx2, ox2, wy2, oy2);
            float dx, dy; unpack2(res, dx, dy);
            step_update(xl[p], yl[p], dx, dy, SPX, SPY);
        }
    }

    int x = x0b + tx;
    #pragma unroll
    for (int p = 0; p < 2; p++) {
        int y = y0b + ty + p * WTY;
        if (y >= HH) continue;

        float xs = clampf(xl[p] + (float)ox, 0.0f, (float)(WW - 1));
        float ys = clampf(yl[p] + (float)oy, 0.0f, (float)(HH - 1));
        int x0 = (int)xs, y0 = (int)ys;
        int x1 = min(x0 + 1, WW - 1), y1 = min(y0 + 1, HH - 1);
        float wx = xs - (float)x0, wy = ys - (float)y0;

        #pragma unroll
        for (int c = 0; c < 3; c++) {
            const float* pp = img + (size_t)(b * 3 + c) * HH * WW;
            float v00 = __ldg(pp + y0 * WW + x0);
            float v01 = __ldg(pp + y0 * WW + x1);
            float v10 = __ldg(pp + y1 * WW + x0);
            float v11 = __ldg(pp + y1 * WW + x1);
            float v = (v00 * (1.0f - wx) + v01 * wx) * (1.0f - wy) +
                      (v10 * (1.0f - wx) + v11 * wx) * wy;
            out[((size_t)(b * 3 + c) * HH + y) * WW + x] = clampf(v, 0.0f, 1.0f);
        }
    }
}

// ---------------- launch ----------------
extern "C" void kernel_launch(void* const* d_in, const int* in_sizes, int n_in,
                              void* d_out, int out_size) {
    const float* img = (const float*)d_in[0];
    float* out = (float*)d_out;

    float* edge;
    float2* grad;
    cudaGetSymbolAddress((void**)&edge, g_edge);
    cudaGetSymbolAddress((void**)&grad, g_grad);

    dim3 bt(TX, TY);
    dim3 gs(SW / TX, (SH + TY - 1) / TY, BB);            // 30 x 34 x 2
    k_edge<<<gs, bt>>>(img, edge);
    k_grad<<<gs, bt>>>(edge, grad);

    dim3 wt(WTX, WTY);                                   // 32 x 8 = 256 threads
    dim3 gw(WW / WTX, (HH + TLH - 1) / TLH, BB);         // 60 x 68 x 2
    k_warp<<<gw, wt>>>(img, grad, out);
}

// round 17
// speedup vs baseline: 1.7818x; 1.0448x over previous
#include <cuda_runtime.h>
#include <math.h>

// Fixed problem shape: image [2, 3, 1080, 1920] float32
#define BB 2
#define HH 1080
#define WW 1920
#define SH 540
#define SW 960
#define NS (BB * SH * SW)

// ---------------- scratch ----------------
__device__ float  g_edge[NS];
__device__ float2 g_grad[NS];   // half-res grad field, interleaved (xg, yg)

// Constant fractional pixel shifts: offset*(N-1)/N per shift_sample derivation.
#define D1X (959.0f / 960.0f)     // sobel offset 1.0, x
#define D1Y (539.0f / 540.0f)     // sobel offset 1.0, y
#define D2X (959.0f / 1920.0f)    // kernel offset 0.5, x
#define D2Y (539.0f / 1080.0f)    // kernel offset 0.5, y

typedef unsigned long long u64;

__device__ __forceinline__ float clampf(float v, float lo, float hi) {
    return fminf(fmaxf(v, lo), hi);
}
__device__ __forceinline__ float gridc(int i, int n) {
    return -1.0f + 2.0f * (float)i / (float)(n - 1);
}
__device__ __forceinline__ int iclamp(int v, int lo, int hi) {
    return min(max(v, lo), hi);
}

// ---- packed f32x2 helpers (sm_103a) ----
__device__ __forceinline__ u64 pack2(float lo, float hi) {
    u64 r; asm("mov.b64 %0, {%1, %2};" : "=l"(r) : "f"(lo), "f"(hi)); return r;
}
__device__ __forceinline__ void unpack2(u64 v, float& lo, float& hi) {
    asm("mov.b64 {%0, %1}, %2;" : "=f"(lo), "=f"(hi) : "l"(v));
}
__device__ __forceinline__ u64 sub2(u64 a, u64 b) {
    u64 r; asm("sub.rn.f32x2 %0, %1, %2;" : "=l"(r) : "l"(a), "l"(b)); return r;
}
__device__ __forceinline__ u64 fma2(u64 a, u64 b, u64 c) {
    u64 r; asm("fma.rn.f32x2 %0, %1, %2, %3;" : "=l"(r) : "l"(a), "l"(b), "l"(c)); return r;
}
// lerp-form bilinear on packed float2: v00 + (v01-v00)wx rows, then y-lerp.
// O(ulp) reassociation of the reference two-sided form (continuous argument).
__device__ __forceinline__ u64 bilin2(u64 v00, u64 v01, u64 v10, u64 v11,
                                      u64 wx2, u64 wy2) {
    u64 a = fma2(sub2(v01, v00), wx2, v00);
    u64 b = fma2(sub2(v11, v10), wx2, v10);
    return fma2(sub2(b, a), wy2, a);
}

// luma of full-res image bilinearly resized to small-res pixel (i, j).
__device__ __forceinline__ float luma_at(const float* __restrict__ img, int b,
                                         int i, int j) {
    float gy = gridc(i, SH), gx = gridc(j, SW);
    float x = clampf((gx + 1.0f) * 0.5f * (float)(WW - 1), 0.0f, (float)(WW - 1));
    float y = clampf((gy + 1.0f) * 0.5f * (float)(HH - 1), 0.0f, (float)(HH - 1));
    int x0 = (int)floorf(x), y0 = (int)floorf(y);
    int x1 = min(x0 + 1, WW - 1), y1 = min(y0 + 1, HH - 1);
    float wx = x - (float)x0, wy = y - (float)y0;

    const float* p0 = img + (size_t)(b * 3 + 0) * HH * WW;
    const float* p1 = img + (size_t)(b * 3 + 1) * HH * WW;
    const float* p2 = img + (size_t)(b * 3 + 2) * HH * WW;
    auto lum = [&](int yy, int xx) -> float {
        int o = yy * WW + xx;
        return 0.299f * __ldg(p0 + o) + 0.587f * __ldg(p1 + o) + 0.114f * __ldg(p2 + o);
    };
    return (lum(y0, x0) * (1.0f - wx) + lum(y0, x1) * wx) * (1.0f - wy) +
           (lum(y1, x0) * (1.0f - wx) + lum(y1, x1) * wx) * wy;
}

// ================= K1: img -> edge  (luma + sobelX(1.0) + sobelY-mag) =========
// (R7 version — measured 19.3us; the streamed-LF variant measured 22.6us.)
#define TX 32
#define TY 16
__global__ void k_edge(const float* __restrict__ img, float* __restrict__ edge) {
    __shared__ float L [TY + 2][TX + 2];   // luma tile, halo 1 (clamp-loaded)
    __shared__ float S0[TY + 2][TX];       // sobelX ch0 (-l + r)
    __shared__ float S1[TY + 2][TX];       // sobelX ch1 (l + 2m + r)

    int b   = blockIdx.z;
    int gj0 = blockIdx.x * TX;
    int gi0 = blockIdx.y * TY;
    int tx = threadIdx.x, ty = threadIdx.y;
    int tid = ty * TX + tx;

    for (int t = tid; t < (TY + 2) * (TX + 2); t += TX * TY) {
        int r = t / (TX + 2), c = t % (TX + 2);
        L[r][c] = luma_at(img, b, iclamp(gi0 - 1 + r, 0, SH - 1),
                                  iclamp(gj0 - 1 + c, 0, SW - 1));
    }
    __syncthreads();

    // sobelX: clamp-loaded halo reproduces reference border clamping exactly.
    for (int t = tid; t < (TY + 2) * TX; t += TX * TY) {
        int r = t / TX, c = t % TX;
        float l  = D1X * L[r][c]     + (1.0f - D1X) * L[r][c + 1];
        float rr = (1.0f - D1X) * L[r][c + 1] + D1X * L[r][c + 2];
        S0[r][c] = rr - l;
        S1[r][c] = l + 2.0f * L[r][c + 1] + rr;
    }
    __syncthreads();

    int gi = gi0 + ty;
    if (gi >= SH) return;

    float t0 = D1Y * S0[ty][tx]     + (1.0f - D1Y) * S0[ty + 1][tx];
    float b0 = (1.0f - D1Y) * S0[ty + 1][tx] + D1Y * S0[ty + 2][tx];
    float t1 = D1Y * S1[ty][tx]     + (1.0f - D1Y) * S1[ty + 1][tx];
    float b1 = (1.0f - D1Y) * S1[ty + 1][tx] + D1Y * S1[ty + 2][tx];
    float xg = (t0 + 2.0f * S0[ty + 1][tx] + b0) * 0.125f;
    float yg = (-t1 + b1) * 0.125f;
    edge[(size_t)b * SH * SW + gi * SW + gj0 + tx] =
        __powf(sqrtf(xg * xg + yg * yg), 0.7f);
}

// ========== K2: edge -> grad  (gaussian blur + kernelX(0.5) + kernelY(0.5)) ===
__global__ void k_grad(const float* __restrict__ edge, float2* __restrict__ grad) {
    __shared__ float E  [TY + 6][TX + 6];
    __shared__ float Bh [TY + 6][TX + 2];
    __shared__ float Bv [TY + 2][TX + 2];
    __shared__ float K0 [TY + 2][TX];
    __shared__ float K1s[TY + 2][TX];

    int b   = blockIdx.z;
    int gj0 = blockIdx.x * TX;
    int gi0 = blockIdx.y * TY;
    int tx = threadIdx.x, ty = threadIdx.y;
    int tid = ty * TX + tx;

    const float k2 = 0.13533528323661270f;
    const float k1 = 0.60653065971263342f;
    const float sum = 2.0f * k2 + 2.0f * k1 + 1.0f;
    const float w0 = k2 / sum, w1 = k1 / sum, w2 = 1.0f / sum;

    const float* sp = edge + (size_t)b * SH * SW;
    for (int t = tid; t < (TY + 6) * (TX + 6); t += TX * TY) {
        int r = t / (TX + 6), c = t % (TX + 6);
        E[r][c] = __ldg(sp + iclamp(gi0 - 3 + r, 0, SH - 1) * SW
                           + iclamp(gj0 - 3 + c, 0, SW - 1));
    }
    __syncthreads();

    for (int t = tid; t < (TY + 6) * (TX + 2); t += TX * TY) {
        int r = t / (TX + 2), c = t % (TX + 2);
        Bh[r][c] = w0 * (E[r][c] + E[r][c + 4]) +
                   w1 * (E[r][c + 1] + E[r][c + 3]) + w2 * E[r][c + 2];
    }
    __syncthreads();

    for (int t = tid; t < (TY + 2) * (TX + 2); t += TX * TY) {
        int r = t / (TX + 2), c = t % (TX + 2);
        Bv[r][c] = w0 * (Bh[r][c] + Bh[r + 4][c]) +
                   w1 * (Bh[r + 1][c] + Bh[r + 3][c]) + w2 * Bh[r + 2][c];
    }
    __syncthreads();

    // kernelX with GLOBAL column clamp (halo blur values != clamped values).
    for (int t = tid; t < (TY + 2) * TX; t += TX * TY) {
        int r = t / TX, c = t % TX;
        int gj = gj0 + c;
        int cl = (gj - 1 >= 0)      ? c     : c + 1;
        int cr = (gj + 1 <= SW - 1) ? c + 2 : c + 1;
        float l  = D2X * Bv[r][cl]  + (1.0f - D2X) * Bv[r][c + 1];
        float rr = (1.0f - D2X) * Bv[r][c + 1] + D2X * Bv[r][cr];
        K0[r][c]  = rr - l;
        K1s[r][c] = l + 2.0f * Bv[r][c + 1] + rr;
    }
    __syncthreads();

    int gi = gi0 + ty;
    if (gi >= SH) return;

    int rt = (gi - 1 >= 0)      ? ty     : ty + 1;
    int rb = (gi + 1 <= SH - 1) ? ty + 2 : ty + 1;
    float t0 = D2Y * K0[rt][tx]  + (1.0f - D2Y) * K0[ty + 1][tx];
    float b0 = (1.0f - D2Y) * K0[ty + 1][tx] + D2Y * K0[rb][tx];
    float t1 = D2Y * K1s[rt][tx] + (1.0f - D2Y) * K1s[ty + 1][tx];
    float b1 = (1.0f - D2Y) * K1s[ty + 1][tx] + D2Y * K1s[rb][tx];

    grad[(size_t)b * SH * SW + gi * SW + gj0 + tx] =
        make_float2((t0 + 2.0f * K0[ty + 1][tx] + b0) * 0.125f,
                    (-t1 + b1) * 0.125f);
}

// ===================== fused upsample + iterative warp ========================
#define WTX 32
#define WTY 8            // thread rows; block covers 32 x 16 output pixels
#define TLH 16
#define GTW (WTX + 2)    // 34
#define GTH (TLH + 2)    // 18

__device__ __forceinline__ void step_update(float& xl, float& yl,
                                            float dx, float dy,
                                            float SPX, float SPY) {
    float f = __fdividef(1.0f, sqrtf(dx * dx + dy * dy) + 0.01f);
    xl -= dx * f * SPX;
    yl -= dy * f * SPY;
}

__global__ void k_warp(const float* __restrict__ img, const float2* __restrict__ grad,
                       float* __restrict__ out) {
    __shared__ float2 s_g[GTH][GTW];
    __shared__ float CWX[GTW];  __shared__ int CX0[GTW];
    __shared__ float CWY[GTH];  __shared__ int CY0[GTH];

    int b   = blockIdx.z;
    int x0b = blockIdx.x * WTX;
    int y0b = blockIdx.y * TLH;
    int ox = x0b - 1, oy = y0b - 1;
    int tx = threadIdx.x, ty = threadIdx.y;
    int tid = ty * WTX + tx;
    const int NT = WTX * WTY;  // 256

    const float2* gp = grad + (size_t)b * SH * SW;
    const float hxs = 959.0f / 1919.0f;
    const float hys = 539.0f / 1079.0f;

    // per-column / per-row upsample coefficients
    if (tid < GTW) {
        int xi = iclamp(ox + tid, 0, WW - 1);
        float hx = fminf((float)xi * hxs, (float)(SW - 1));
        int h0 = (int)hx;
        CX0[tid] = h0; CWX[tid] = hx - (float)h0;
    } else if (tid < GTW + GTH) {
        int k = tid - GTW;
        int yi = iclamp(oy + k, 0, HH - 1);
        float hy = fminf((float)yi * hys, (float)(SH - 1));
        int h0 = (int)hy;
        CY0[k] = h0; CWY[k] = hy - (float)h0;
    }
    __syncthreads();

    // tile fill: full-res grad = bilinear upsample of half-res grad (f32x2 lerp)
    for (int t = tid; t < GTH * GTW; t += NT) {
        int r = t / GTW, c = t % GTW;
        int hx0 = CX0[c], hy0 = CY0[r];
        float wx = CWX[c], wy = CWY[r];
        int hx1 = min(hx0 + 1, SW - 1), hy1 = min(hy0 + 1, SH - 1);
        const u64* row0 = (const u64*)(gp + hy0 * SW);
        const u64* row1 = (const u64*)(gp + hy1 * SW);
        u64 v00 = __ldg(row0 + hx0), v01 = __ldg(row0 + hx1);
        u64 v10 = __ldg(row1 + hx0), v11 = __ldg(row1 + hx1);
        *(u64*)&s_g[r][c] = bilin2(v00, v01, v10, v11,
                                   pack2(wx, wx), pack2(wy, wy));
    }
    __syncthreads();

    // local pixel coordinates; pos accumulates UNclamped, clamped copies sample.
    const float xlo = (float)(-ox), xhi = (float)(WW - 1 - ox);
    const float ylo = (float)(-oy), yhi = (float)(HH - 1 - oy);
    const float SPX = 0.1f * 1919.0f / 1920.0f;
    const float SPY = 0.1f * 1079.0f / 1080.0f;

    float xl[2], yl[2];
    xl[0] = (float)(tx + 1);  yl[0] = (float)(ty + 1);
    xl[1] = (float)(tx + 1);  yl[1] = (float)(ty + 9);

    // iteration 1: start pos is exactly a texel (integral coords, clamp no-op,
    // wx=wy=0) -> bilinear degenerates to a single direct read. Exact.
    {
        float2 ga = s_g[ty + 1][tx + 1];
        float2 gb = s_g[ty + 9][tx + 1];
        step_update(xl[0], yl[0], ga.x, ga.y, SPX, SPY);
        step_update(xl[1], yl[1], gb.x, gb.y, SPX, SPY);
    }

    // iterations 2..6: general bilinear (f32x2 lerp), 2 independent chains
    #pragma unroll
    for (int it = 0; it < 5; it++) {
        #pragma unroll
        for (int p = 0; p < 2; p++) {
            float xc = clampf(xl[p], xlo, xhi);
            float yc = clampf(yl[p], ylo, yhi);
            int x0i = (int)xc, y0i = (int)yc;   // nonneg: cast == floor
            float wx = xc - (float)x0i, wy = yc - (float)y0i;
            const u64* base = (const u64*)&s_g[y0i][x0i];
            u64 v00 = base[0], v01 = base[1];
            u64 v10 = base[GTW], v11 = base[GTW + 1];
            u64 res = bilin2(v00, v01, v10, v11,
                             pack2(wx, wx), pack2(wy, wy));
            float dx, dy; unpack2(res, dx, dy);
            step_update(xl[p], yl[p], dx, dy, SPX, SPY);
        }
    }

    int x = x0b + tx;
    #pragma unroll
    for (int p = 0; p < 2; p++) {
        int y = y0b + ty + p * WTY;
        if (y >= HH) continue;

        float xs = clampf(xl[p] + (float)ox, 0.0f, (float)(WW - 1));
        float ys = clampf(yl[p] + (float)oy, 0.0f, (float)(HH - 1));
        int x0 = (int)xs, y0 = (int)ys;
        int x1 = min(x0 + 1, WW - 1), y1 = min(y0 + 1, HH - 1);
        float wx = xs - (float)x0, wy = ys - (float)y0;

        #pragma unroll
        for (int c = 0; c < 3; c++) {
            const float* pp = img + (size_t)(b * 3 + c) * HH * WW;
            float v00 = __ldg(pp + y0 * WW + x0);
            float v01 = __ldg(pp + y0 * WW + x1);
            float v10 = __ldg(pp + y1 * WW + x0);
            float v11 = __ldg(pp + y1 * WW + x1);
            float v = (v00 * (1.0f - wx) + v01 * wx) * (1.0f - wy) +
                      (v10 * (1.0f - wx) + v11 * wx) * wy;
            out[((size_t)(b * 3 + c) * HH + y) * WW + x] = clampf(v, 0.0f, 1.0f);
        }
    }
}

// ---------------- launch ----------------
extern "C" void kernel_launch(void* const* d_in, const int* in_sizes, int n_in,
                              void* d_out, int out_size) {
    const float* img = (const float*)d_in[0];
    float* out = (float*)d_out;

    float* edge;
    float2* grad;
    cudaGetSymbolAddress((void**)&edge, g_edge);
    cudaGetSymbolAddress((void**)&grad, g_grad);

    dim3 bt(TX, TY);
    dim3 gs(SW / TX, (SH + TY - 1) / TY, BB);            // 30 x 34 x 2
    k_edge<<<gs, bt>>>(img, edge);
    k_grad<<<gs, bt>>>(edge, grad);

    dim3 wt(WTX, WTY);                                   // 32 x 8 = 256 threads
    dim3 gw(WW / WTX, (HH + TLH - 1) / TLH, BB);         // 60 x 68 x 2
    k_warp<<<gw, wt>>>(img, grad, out);
}